// round 1
// baseline (speedup 1.0000x reference)
#include <cuda_runtime.h>

// Problem constants
#define M_ROWS 4096   // B*S
#define D_MODEL 512
#define FF_DIM 2048
#define NQ (4096*512) // elements in one [B,S,D] buffer

// Scratch: q, k, v, attn, Z (5 x 2M floats) + ff (8M floats) = 75.5 MB
__device__ float g_scratch[5 * NQ + 4096 * 2048];

// ---------------------------------------------------------------------------
// Generic tiled fp32 GEMM: C[M,N] = A[M,K] @ W[K,N] (+bias[N]) (+res[M,N])
// 64x64 block tile, BK=16, 256 threads, 4x4 register micro-tile.
// Requires M%64==0, N%64==0, K%16==0 (true for all our shapes).
// ---------------------------------------------------------------------------
__global__ __launch_bounds__(256) void gemm64(
    const float* __restrict__ A, const float* __restrict__ W,
    const float* __restrict__ bias, const float* __restrict__ res,
    float* __restrict__ C, int M, int N, int K)
{
    __shared__ float As[16][68];   // [k][m], padded to 68 (16B-aligned rows)
    __shared__ float Bs[16][64];   // [k][n]

    const int tid = threadIdx.x;
    const int tx = tid & 15;
    const int ty = tid >> 4;
    const int bm = blockIdx.y * 64;
    const int bn = blockIdx.x * 64;

    const int ar = tid >> 2;          // A tile row 0..63
    const int ac = (tid & 3) * 4;     // A tile col 0,4,8,12
    const int br = tid >> 4;          // B tile row 0..15
    const int bc = (tid & 15) * 4;    // B tile col 0..60

    float c[4][4] = {};

    for (int k0 = 0; k0 < K; k0 += 16) {
        float4 av = *(const float4*)(A + (size_t)(bm + ar) * K + k0 + ac);
        As[ac + 0][ar] = av.x;
        As[ac + 1][ar] = av.y;
        As[ac + 2][ar] = av.z;
        As[ac + 3][ar] = av.w;
        *(float4*)&Bs[br][bc] =
            *(const float4*)(W + (size_t)(k0 + br) * N + bn + bc);
        __syncthreads();

#pragma unroll
        for (int kk = 0; kk < 16; kk++) {
            float a[4], b[4];
            *(float4*)a = *(const float4*)&As[kk][ty * 4];
            *(float4*)b = *(const float4*)&Bs[kk][tx * 4];
#pragma unroll
            for (int i = 0; i < 4; i++)
#pragma unroll
                for (int j = 0; j < 4; j++)
                    c[i][j] = fmaf(a[i], b[j], c[i][j]);
        }
        __syncthreads();
    }

#pragma unroll
    for (int i = 0; i < 4; i++) {
        int row = bm + ty * 4 + i;
        float4 v;
        float* vv = (float*)&v;
#pragma unroll
        for (int j = 0; j < 4; j++) {
            float val = c[i][j];
            if (bias) val += bias[bn + tx * 4 + j];
            vv[j] = val;
        }
        if (res) {
            float4 r = *(const float4*)(res + (size_t)row * N + bn + tx * 4);
            v.x += r.x; v.y += r.y; v.z += r.z; v.w += r.w;
        }
        *(float4*)(C + (size_t)row * N + bn + tx * 4) = v;
    }
}

// ---------------------------------------------------------------------------
// Batched flash attention over the reinterpreted [16, 2048, 64] layout.
// One query per thread, 128 queries per block. K/V streamed in 64-key tiles.
// scores = (q . k) / sqrt(512); online softmax with chunk-of-16 max update.
// ---------------------------------------------------------------------------
__global__ __launch_bounds__(128) void attn_kernel(
    const float* __restrict__ q, const float* __restrict__ k,
    const float* __restrict__ v, float* __restrict__ o)
{
    __shared__ float Ks[64 * 64];
    __shared__ float Vs[64 * 64];

    const int g   = blockIdx.y;                 // 0..15 pseudo-head
    const int tid = threadIdx.x;
    const int qi  = blockIdx.x * 128 + tid;     // query row within g
    const float scale = 0.04419417382415922f;   // 1/sqrt(512)

    float4 qv[16];
    const float4* qr = (const float4*)(q + ((size_t)g * 2048 + qi) * 64);
#pragma unroll
    for (int t = 0; t < 16; t++) qv[t] = qr[t];

    float4 acc[16];
#pragma unroll
    for (int t = 0; t < 16; t++) acc[t] = make_float4(0.f, 0.f, 0.f, 0.f);
    float m = -1e30f, l = 0.f;

    for (int kt = 0; kt < 32; kt++) {
        __syncthreads();
        const float4* kg = (const float4*)(k + ((size_t)g * 2048 + kt * 64) * 64);
        const float4* vg = (const float4*)(v + ((size_t)g * 2048 + kt * 64) * 64);
#pragma unroll
        for (int i = 0; i < 8; i++) {
            ((float4*)Ks)[tid + i * 128] = kg[tid + i * 128];
            ((float4*)Vs)[tid + i * 128] = vg[tid + i * 128];
        }
        __syncthreads();

#pragma unroll
        for (int c = 0; c < 4; c++) {      // 4 chunks of 16 keys
            float s[16];
#pragma unroll
            for (int jj = 0; jj < 16; jj++) {
                const float4* kr = (const float4*)(Ks + (c * 16 + jj) * 64);
                float sv = 0.f;
#pragma unroll
                for (int t = 0; t < 16; t++) {
                    float4 kk4 = kr[t];
                    sv = fmaf(qv[t].x, kk4.x, sv);
                    sv = fmaf(qv[t].y, kk4.y, sv);
                    sv = fmaf(qv[t].z, kk4.z, sv);
                    sv = fmaf(qv[t].w, kk4.w, sv);
                }
                s[jj] = sv * scale;
            }
            float mloc = s[0];
#pragma unroll
            for (int jj = 1; jj < 16; jj++) mloc = fmaxf(mloc, s[jj]);
            if (mloc > m) {
                float r = __expf(m - mloc);
                l *= r;
#pragma unroll
                for (int t = 0; t < 16; t++) {
                    acc[t].x *= r; acc[t].y *= r; acc[t].z *= r; acc[t].w *= r;
                }
                m = mloc;
            }
#pragma unroll
            for (int jj = 0; jj < 16; jj++) {
                float p = __expf(s[jj] - m);
                l += p;
                const float4* vr = (const float4*)(Vs + (c * 16 + jj) * 64);
#pragma unroll
                for (int t = 0; t < 16; t++) {
                    float4 vv = vr[t];
                    acc[t].x = fmaf(p, vv.x, acc[t].x);
                    acc[t].y = fmaf(p, vv.y, acc[t].y);
                    acc[t].z = fmaf(p, vv.z, acc[t].z);
                    acc[t].w = fmaf(p, vv.w, acc[t].w);
                }
            }
        }
    }

    float inv = 1.f / l;
    float4* orow = (float4*)(o + ((size_t)g * 2048 + qi) * 64);
#pragma unroll
    for (int t = 0; t < 16; t++) {
        float4 a = acc[t];
        orow[t] = make_float4(a.x * inv, a.y * inv, a.z * inv, a.w * inv);
    }
}

// ---------------------------------------------------------------------------
// In-place layernorm over D=512 per row. One block per row, 512 threads.
// ---------------------------------------------------------------------------
__global__ __launch_bounds__(512) void ln512(
    float* __restrict__ x, const float* __restrict__ gamma,
    const float* __restrict__ beta)
{
    const int row = blockIdx.x;
    const int tid = threadIdx.x;
    float* p = x + (size_t)row * 512;
    float v = p[tid];
    float s = v, sq = v * v;
#pragma unroll
    for (int off = 16; off > 0; off >>= 1) {
        s  += __shfl_xor_sync(0xffffffffu, s, off);
        sq += __shfl_xor_sync(0xffffffffu, sq, off);
    }
    __shared__ float ws[16], wq[16];
    __shared__ float stats[2];
    if ((tid & 31) == 0) { ws[tid >> 5] = s; wq[tid >> 5] = sq; }
    __syncthreads();
    if (tid == 0) {
        float S = 0.f, SQ = 0.f;
#pragma unroll
        for (int i = 0; i < 16; i++) { S += ws[i]; SQ += wq[i]; }
        float mu  = S * (1.f / 512.f);
        float var = SQ * (1.f / 512.f) - mu * mu;
        stats[0] = mu;
        stats[1] = rsqrtf(var + 1e-5f);
    }
    __syncthreads();
    p[tid] = (v - stats[0]) * stats[1] * gamma[tid] + beta[tid];
}

// ---------------------------------------------------------------------------
extern "C" void kernel_launch(void* const* d_in, const int* in_sizes, int n_in,
                              void* d_out, int out_size)
{
    (void)in_sizes; (void)n_in; (void)out_size;
    const float* Q     = (const float*)d_in[0];
    const float* K     = (const float*)d_in[1];
    const float* V     = (const float*)d_in[2];
    // d_in[3] = mask (unused by the reference math)
    const float* Wq    = (const float*)d_in[4];
    const float* Wk    = (const float*)d_in[5];
    const float* Wv    = (const float*)d_in[6];
    const float* Wo    = (const float*)d_in[7];
    const float* bo    = (const float*)d_in[8];
    const float* gamma = (const float*)d_in[9];
    const float* beta  = (const float*)d_in[10];
    const float* W1    = (const float*)d_in[11];
    const float* b1    = (const float*)d_in[12];
    const float* W2    = (const float*)d_in[13];
    const float* b2    = (const float*)d_in[14];
    float* out = (float*)d_out;

    float* base = nullptr;
    cudaGetSymbolAddress((void**)&base, g_scratch);
    float* gq    = base;
    float* gk    = base + (size_t)NQ;
    float* gv    = base + (size_t)2 * NQ;
    float* gattn = base + (size_t)3 * NQ;
    float* gZ    = base + (size_t)4 * NQ;
    float* gff   = base + (size_t)5 * NQ;

    dim3 gp(D_MODEL / 64, M_ROWS / 64);   // (8, 64) for N=512 GEMMs
    dim3 gf(FF_DIM / 64, M_ROWS / 64);    // (32, 64) for FFN1

    // Q/K/V projections
    gemm64<<<gp, 256>>>(Q, Wq, nullptr, nullptr, gq, M_ROWS, D_MODEL, D_MODEL);
    gemm64<<<gp, 256>>>(K, Wk, nullptr, nullptr, gk, M_ROWS, D_MODEL, D_MODEL);
    gemm64<<<gp, 256>>>(V, Wv, nullptr, nullptr, gv, M_ROWS, D_MODEL, D_MODEL);

    // Batched attention over reinterpreted [16, 2048, 64]
    attn_kernel<<<dim3(16, 16), 128>>>(gq, gk, gv, gattn);

    // Output projection + bias + residual (X = V), then LN -> Z
    gemm64<<<gp, 256>>>(gattn, Wo, bo, V, gZ, M_ROWS, D_MODEL, D_MODEL);
    ln512<<<M_ROWS, 512>>>(gZ, gamma, beta);

    // FFN (no activation in the reference)
    gemm64<<<gf, 256>>>(gZ, W1, b1, nullptr, gff, M_ROWS, FF_DIM, D_MODEL);
    gemm64<<<gp, 256>>>(gff, W2, b2, gZ, out, M_ROWS, D_MODEL, FF_DIM);
    ln512<<<M_ROWS, 512>>>(out, gamma, beta);
}

// round 2
// speedup vs baseline: 1.3876x; 1.3876x over previous
#include <cuda_runtime.h>

#define M_ROWS 4096
#define D_MODEL 512
#define FF_DIM 2048
#define NQ (4096*512)

__device__ float g_scratch[5 * NQ + 4096 * 2048];

// ---------------------------------------------------------------------------
// tf32 helpers
// ---------------------------------------------------------------------------
__device__ __forceinline__ unsigned f2tf(float f) {
    unsigned r;
    asm("cvt.rna.tf32.f32 %0, %1;" : "=r"(r) : "f"(f));
    return r;
}

__device__ __forceinline__ void mma_tf32(float d[4], const unsigned a[4],
                                         const unsigned b[2], const float c[4]) {
    asm volatile(
        "mma.sync.aligned.m16n8k8.row.col.f32.tf32.tf32.f32 "
        "{%0,%1,%2,%3}, {%4,%5,%6,%7}, {%8,%9}, {%10,%11,%12,%13};"
        : "=f"(d[0]), "=f"(d[1]), "=f"(d[2]), "=f"(d[3])
        : "r"(a[0]), "r"(a[1]), "r"(a[2]), "r"(a[3]),
          "r"(b[0]), "r"(b[1]),
          "f"(c[0]), "f"(c[1]), "f"(c[2]), "f"(c[3]));
}

// ---------------------------------------------------------------------------
// tf32 tensor-core GEMM core: C[M,N] = A[M,K] @ W[K,N] (+bias) (+res)
// Block tile 64x128, BK=32, 256 threads (8 warps as 2x4), warp tile 32x32.
// Fragment smem layouts chosen conflict-free:
//   As[64][36]  (row-major, pad 4): frag bank = lane  -> conflict-free
//   Bs[32][136] (row-major, pad 8): bank = 8k+n       -> conflict-free
// ---------------------------------------------------------------------------
__device__ __forceinline__ void gemm_core(
    const float* __restrict__ A, const float* __restrict__ W,
    const float* __restrict__ bias, const float* __restrict__ res,
    float* __restrict__ C, int M, int N, int K)
{
    __shared__ unsigned As[64 * 36];
    __shared__ unsigned Bs[32 * 136];

    const int tid  = threadIdx.x;
    const int lane = tid & 31;
    const int warp = tid >> 5;
    const int wm   = warp & 1;   // 0..1 -> 32 rows each
    const int wn   = warp >> 1;  // 0..3 -> 32 cols each
    const int gr   = lane >> 2;  // 0..7
    const int gc   = lane & 3;   // 0..3

    const int bm = blockIdx.y * 64;
    const int bn = blockIdx.x * 128;

    float acc[2][4][4] = {};

    for (int k0 = 0; k0 < K; k0 += 32) {
        // Load A tile 64x32 (2 passes of 32 rows; 8 threads/row, float4)
#pragma unroll
        for (int i = 0; i < 2; i++) {
            int m  = i * 32 + (tid >> 3);
            int c4 = (tid & 7) * 4;
            float4 v = *(const float4*)(A + (size_t)(bm + m) * K + k0 + c4);
            uint4 t = make_uint4(f2tf(v.x), f2tf(v.y), f2tf(v.z), f2tf(v.w));
            *(uint4*)&As[m * 36 + c4] = t;
        }
        // Load B tile 32x128 (each warp 4 rows, 1 float4/lane/row)
#pragma unroll
        for (int i = 0; i < 4; i++) {
            int r  = warp * 4 + i;
            int n4 = lane * 4;
            float4 v = *(const float4*)(W + (size_t)(k0 + r) * N + bn + n4);
            uint4 t = make_uint4(f2tf(v.x), f2tf(v.y), f2tf(v.z), f2tf(v.w));
            *(uint4*)&Bs[r * 136 + n4] = t;
        }
        __syncthreads();

#pragma unroll
        for (int ks = 0; ks < 4; ks++) {
            unsigned a[2][4], b[4][2];
#pragma unroll
            for (int mt = 0; mt < 2; mt++) {
                int row = wm * 32 + mt * 16 + gr;
                int col = ks * 8 + gc;
                a[mt][0] = As[row * 36 + col];
                a[mt][1] = As[(row + 8) * 36 + col];
                a[mt][2] = As[row * 36 + col + 4];
                a[mt][3] = As[(row + 8) * 36 + col + 4];
            }
#pragma unroll
            for (int nt = 0; nt < 4; nt++) {
                int bc = wn * 32 + nt * 8 + gr;
                int kr = ks * 8 + gc;
                b[nt][0] = Bs[kr * 136 + bc];
                b[nt][1] = Bs[(kr + 4) * 136 + bc];
            }
#pragma unroll
            for (int mt = 0; mt < 2; mt++)
#pragma unroll
                for (int nt = 0; nt < 4; nt++)
                    mma_tf32(acc[mt][nt], a[mt], b[nt], acc[mt][nt]);
        }
        __syncthreads();
    }

    // Epilogue: C-frag (r,2c),(r,2c+1),(r+8,2c),(r+8,2c+1)
#pragma unroll
    for (int mt = 0; mt < 2; mt++) {
#pragma unroll
        for (int nt = 0; nt < 4; nt++) {
            int r0  = bm + wm * 32 + mt * 16 + gr;
            int col = bn + wn * 32 + nt * 8 + 2 * gc;
            float v0 = acc[mt][nt][0];
            float v1 = acc[mt][nt][1];
            float v2 = acc[mt][nt][2];
            float v3 = acc[mt][nt][3];
            if (bias) {
                float b0 = bias[col], b1 = bias[col + 1];
                v0 += b0; v1 += b1; v2 += b0; v3 += b1;
            }
            if (res) {
                float2 r0v = *(const float2*)(res + (size_t)r0 * N + col);
                float2 r1v = *(const float2*)(res + (size_t)(r0 + 8) * N + col);
                v0 += r0v.x; v1 += r0v.y; v2 += r1v.x; v3 += r1v.y;
            }
            *(float2*)(C + (size_t)r0 * N + col)       = make_float2(v0, v1);
            *(float2*)(C + (size_t)(r0 + 8) * N + col) = make_float2(v2, v3);
        }
    }
}

__global__ __launch_bounds__(256) void gemm_one(
    const float* __restrict__ A, const float* __restrict__ W,
    const float* __restrict__ bias, const float* __restrict__ res,
    float* __restrict__ C, int M, int N, int K)
{
    gemm_core(A, W, bias, res, C, M, N, K);
}

__global__ __launch_bounds__(256) void gemm_qkv(
    const float* __restrict__ Q, const float* __restrict__ K_,
    const float* __restrict__ V,
    const float* __restrict__ Wq, const float* __restrict__ Wk,
    const float* __restrict__ Wv,
    float* __restrict__ gq, float* __restrict__ gk, float* __restrict__ gv,
    int M, int N, int K)
{
    int z = blockIdx.z;
    const float* A = (z == 0) ? Q : (z == 1) ? K_ : V;
    const float* W = (z == 0) ? Wq : (z == 1) ? Wk : Wv;
    float* C       = (z == 0) ? gq : (z == 1) ? gk : gv;
    gemm_core(A, W, nullptr, nullptr, C, M, N, K);
}

// ---------------------------------------------------------------------------
// Flash attention, [16, 2048, 64] reinterpreted layout.
// 64 queries/block, 128 threads: lane pair (2i, 2i+1) shares one query,
// each thread owns 32 of 64 dims. Halves regs vs R0 -> 2x occupancy.
// ---------------------------------------------------------------------------
__global__ __launch_bounds__(128) void attn_kernel(
    const float* __restrict__ q, const float* __restrict__ k,
    const float* __restrict__ v, float* __restrict__ o)
{
    __shared__ float Ks[64 * 64];
    __shared__ float Vs[64 * 64];

    const int g    = blockIdx.y;
    const int tid  = threadIdx.x;
    const int half = tid & 1;                       // which 32-dim half
    const int qi   = blockIdx.x * 64 + (tid >> 1);  // query row in group
    const float scale = 0.04419417382415922f;       // 1/sqrt(512)

    float4 qv[8];
    const float4* qr =
        (const float4*)(q + ((size_t)g * 2048 + qi) * 64 + half * 32);
#pragma unroll
    for (int t = 0; t < 8; t++) qv[t] = qr[t];

    float4 acc[8];
#pragma unroll
    for (int t = 0; t < 8; t++) acc[t] = make_float4(0.f, 0.f, 0.f, 0.f);
    float m = -1e30f, l = 0.f;

    for (int kt = 0; kt < 32; kt++) {
        __syncthreads();
        const float4* kg = (const float4*)(k + ((size_t)g * 2048 + kt * 64) * 64);
        const float4* vg = (const float4*)(v + ((size_t)g * 2048 + kt * 64) * 64);
#pragma unroll
        for (int i = 0; i < 8; i++) {
            ((float4*)Ks)[tid + i * 128] = kg[tid + i * 128];
            ((float4*)Vs)[tid + i * 128] = vg[tid + i * 128];
        }
        __syncthreads();

#pragma unroll
        for (int c = 0; c < 4; c++) {
            float s[16];
#pragma unroll
            for (int jj = 0; jj < 16; jj++) {
                const float4* kr =
                    (const float4*)(Ks + (c * 16 + jj) * 64 + half * 32);
                float sv = 0.f;
#pragma unroll
                for (int t = 0; t < 8; t++) {
                    float4 kk4 = kr[t];
                    sv = fmaf(qv[t].x, kk4.x, sv);
                    sv = fmaf(qv[t].y, kk4.y, sv);
                    sv = fmaf(qv[t].z, kk4.z, sv);
                    sv = fmaf(qv[t].w, kk4.w, sv);
                }
                sv += __shfl_xor_sync(0xffffffffu, sv, 1);
                s[jj] = sv * scale;
            }
            float mloc = s[0];
#pragma unroll
            for (int jj = 1; jj < 16; jj++) mloc = fmaxf(mloc, s[jj]);
            if (mloc > m) {
                float r = __expf(m - mloc);
                l *= r;
#pragma unroll
                for (int t = 0; t < 8; t++) {
                    acc[t].x *= r; acc[t].y *= r; acc[t].z *= r; acc[t].w *= r;
                }
                m = mloc;
            }
#pragma unroll
            for (int jj = 0; jj < 16; jj++) {
                float p = __expf(s[jj] - m);
                l += p;
                const float4* vr =
                    (const float4*)(Vs + (c * 16 + jj) * 64 + half * 32);
#pragma unroll
                for (int t = 0; t < 8; t++) {
                    float4 vv = vr[t];
                    acc[t].x = fmaf(p, vv.x, acc[t].x);
                    acc[t].y = fmaf(p, vv.y, acc[t].y);
                    acc[t].z = fmaf(p, vv.z, acc[t].z);
                    acc[t].w = fmaf(p, vv.w, acc[t].w);
                }
            }
        }
    }

    float inv = 1.f / l;
    float4* orow = (float4*)(o + ((size_t)g * 2048 + qi) * 64 + half * 32);
#pragma unroll
    for (int t = 0; t < 8; t++) {
        float4 a = acc[t];
        orow[t] = make_float4(a.x * inv, a.y * inv, a.z * inv, a.w * inv);
    }
}

// ---------------------------------------------------------------------------
// In-place layernorm over D=512 per row.
// ---------------------------------------------------------------------------
__global__ __launch_bounds__(512) void ln512(
    float* __restrict__ x, const float* __restrict__ gamma,
    const float* __restrict__ beta)
{
    const int row = blockIdx.x;
    const int tid = threadIdx.x;
    float* p = x + (size_t)row * 512;
    float v = p[tid];
    float s = v, sq = v * v;
#pragma unroll
    for (int off = 16; off > 0; off >>= 1) {
        s  += __shfl_xor_sync(0xffffffffu, s, off);
        sq += __shfl_xor_sync(0xffffffffu, sq, off);
    }
    __shared__ float ws[16], wq[16];
    __shared__ float stats[2];
    if ((tid & 31) == 0) { ws[tid >> 5] = s; wq[tid >> 5] = sq; }
    __syncthreads();
    if (tid == 0) {
        float S = 0.f, SQ = 0.f;
#pragma unroll
        for (int i = 0; i < 16; i++) { S += ws[i]; SQ += wq[i]; }
        float mu  = S * (1.f / 512.f);
        float var = SQ * (1.f / 512.f) - mu * mu;
        stats[0] = mu;
        stats[1] = rsqrtf(var + 1e-5f);
    }
    __syncthreads();
    p[tid] = (v - stats[0]) * stats[1] * gamma[tid] + beta[tid];
}

// ---------------------------------------------------------------------------
extern "C" void kernel_launch(void* const* d_in, const int* in_sizes, int n_in,
                              void* d_out, int out_size)
{
    (void)in_sizes; (void)n_in; (void)out_size;
    const float* Q     = (const float*)d_in[0];
    const float* K     = (const float*)d_in[1];
    const float* V     = (const float*)d_in[2];
    const float* Wq    = (const float*)d_in[4];
    const float* Wk    = (const float*)d_in[5];
    const float* Wv    = (const float*)d_in[6];
    const float* Wo    = (const float*)d_in[7];
    const float* bo    = (const float*)d_in[8];
    const float* gamma = (const float*)d_in[9];
    const float* beta  = (const float*)d_in[10];
    const float* W1    = (const float*)d_in[11];
    const float* b1    = (const float*)d_in[12];
    const float* W2    = (const float*)d_in[13];
    const float* b2    = (const float*)d_in[14];
    float* out = (float*)d_out;

    float* base = nullptr;
    cudaGetSymbolAddress((void**)&base, g_scratch);
    float* gq    = base;
    float* gk    = base + (size_t)NQ;
    float* gv    = base + (size_t)2 * NQ;
    float* gattn = base + (size_t)3 * NQ;
    float* gZ    = base + (size_t)4 * NQ;
    float* gff   = base + (size_t)5 * NQ;

    // QKV projections (fused into one launch, 768 blocks)
    gemm_qkv<<<dim3(D_MODEL / 128, M_ROWS / 64, 3), 256>>>(
        Q, K, V, Wq, Wk, Wv, gq, gk, gv, M_ROWS, D_MODEL, D_MODEL);

    // Batched attention over reinterpreted [16, 2048, 64]
    attn_kernel<<<dim3(32, 16), 128>>>(gq, gk, gv, gattn);

    // Output projection + bias + residual (X = V), then LN -> Z
    gemm_one<<<dim3(D_MODEL / 128, M_ROWS / 64), 256>>>(
        gattn, Wo, bo, V, gZ, M_ROWS, D_MODEL, D_MODEL);
    ln512<<<M_ROWS, 512>>>(gZ, gamma, beta);

    // FFN (no activation in the reference)
    gemm_one<<<dim3(FF_DIM / 128, M_ROWS / 64), 256>>>(
        gZ, W1, b1, nullptr, gff, M_ROWS, FF_DIM, D_MODEL);
    gemm_one<<<dim3(D_MODEL / 128, M_ROWS / 64), 256>>>(
        gff, W2, b2, gZ, out, M_ROWS, D_MODEL, FF_DIM);
    ln512<<<M_ROWS, 512>>>(out, gamma, beta);
}

// round 4
// speedup vs baseline: 4.4698x; 3.2212x over previous
#include <cuda_runtime.h>

#define M_ROWS 4096
#define D_MODEL 512
#define FF_DIM 2048
#define NQ (4096*512)

__device__ float g_scratch[5 * NQ + 4096 * 2048];

// ---------------------------------------------------------------------------
// tf32 helpers
// ---------------------------------------------------------------------------
__device__ __forceinline__ unsigned f2tf(float f) {
    unsigned r;
    asm("cvt.rna.tf32.f32 %0, %1;" : "=r"(r) : "f"(f));
    return r;
}

__device__ __forceinline__ void mma_tf32(float d[4], const unsigned a[4],
                                         const unsigned b0, const unsigned b1,
                                         const float c[4]) {
    asm volatile(
        "mma.sync.aligned.m16n8k8.row.col.f32.tf32.tf32.f32 "
        "{%0,%1,%2,%3}, {%4,%5,%6,%7}, {%8,%9}, {%10,%11,%12,%13};"
        : "=f"(d[0]), "=f"(d[1]), "=f"(d[2]), "=f"(d[3])
        : "r"(a[0]), "r"(a[1]), "r"(a[2]), "r"(a[3]),
          "r"(b0), "r"(b1),
          "f"(c[0]), "f"(c[1]), "f"(c[2]), "f"(c[3]));
}

// ---------------------------------------------------------------------------
// tf32 tensor-core GEMM (unchanged from R1): C = A@W (+bias) (+res)
// ---------------------------------------------------------------------------
__device__ __forceinline__ void gemm_core(
    const float* __restrict__ A, const float* __restrict__ W,
    const float* __restrict__ bias, const float* __restrict__ res,
    float* __restrict__ C, int M, int N, int K)
{
    __shared__ unsigned As[64 * 36];
    __shared__ unsigned Bs[32 * 136];

    const int tid  = threadIdx.x;
    const int lane = tid & 31;
    const int warp = tid >> 5;
    const int wm   = warp & 1;
    const int wn   = warp >> 1;
    const int gr   = lane >> 2;
    const int gc   = lane & 3;

    const int bm = blockIdx.y * 64;
    const int bn = blockIdx.x * 128;

    float acc[2][4][4] = {};

    for (int k0 = 0; k0 < K; k0 += 32) {
#pragma unroll
        for (int i = 0; i < 2; i++) {
            int m  = i * 32 + (tid >> 3);
            int c4 = (tid & 7) * 4;
            float4 v = *(const float4*)(A + (size_t)(bm + m) * K + k0 + c4);
            uint4 t = make_uint4(f2tf(v.x), f2tf(v.y), f2tf(v.z), f2tf(v.w));
            *(uint4*)&As[m * 36 + c4] = t;
        }
#pragma unroll
        for (int i = 0; i < 4; i++) {
            int r  = warp * 4 + i;
            int n4 = lane * 4;
            float4 v = *(const float4*)(W + (size_t)(k0 + r) * N + bn + n4);
            uint4 t = make_uint4(f2tf(v.x), f2tf(v.y), f2tf(v.z), f2tf(v.w));
            *(uint4*)&Bs[r * 136 + n4] = t;
        }
        __syncthreads();

#pragma unroll
        for (int ks = 0; ks < 4; ks++) {
            unsigned a[2][4], b[4][2];
#pragma unroll
            for (int mt = 0; mt < 2; mt++) {
                int row = wm * 32 + mt * 16 + gr;
                int col = ks * 8 + gc;
                a[mt][0] = As[row * 36 + col];
                a[mt][1] = As[(row + 8) * 36 + col];
                a[mt][2] = As[row * 36 + col + 4];
                a[mt][3] = As[(row + 8) * 36 + col + 4];
            }
#pragma unroll
            for (int nt = 0; nt < 4; nt++) {
                int bc = wn * 32 + nt * 8 + gr;
                int kr = ks * 8 + gc;
                b[nt][0] = Bs[kr * 136 + bc];
                b[nt][1] = Bs[(kr + 4) * 136 + bc];
            }
#pragma unroll
            for (int mt = 0; mt < 2; mt++)
#pragma unroll
                for (int nt = 0; nt < 4; nt++)
                    mma_tf32(acc[mt][nt], a[mt], b[nt][0], b[nt][1], acc[mt][nt]);
        }
        __syncthreads();
    }

#pragma unroll
    for (int mt = 0; mt < 2; mt++) {
#pragma unroll
        for (int nt = 0; nt < 4; nt++) {
            int r0  = bm + wm * 32 + mt * 16 + gr;
            int col = bn + wn * 32 + nt * 8 + 2 * gc;
            float v0 = acc[mt][nt][0];
            float v1 = acc[mt][nt][1];
            float v2 = acc[mt][nt][2];
            float v3 = acc[mt][nt][3];
            if (bias) {
                float b0 = bias[col], b1 = bias[col + 1];
                v0 += b0; v1 += b1; v2 += b0; v3 += b1;
            }
            if (res) {
                float2 r0v = *(const float2*)(res + (size_t)r0 * N + col);
                float2 r1v = *(const float2*)(res + (size_t)(r0 + 8) * N + col);
                v0 += r0v.x; v1 += r0v.y; v2 += r1v.x; v3 += r1v.y;
            }
            *(float2*)(C + (size_t)r0 * N + col)       = make_float2(v0, v1);
            *(float2*)(C + (size_t)(r0 + 8) * N + col) = make_float2(v2, v3);
        }
    }
}

__global__ __launch_bounds__(256) void gemm_one(
    const float* __restrict__ A, const float* __restrict__ W,
    const float* __restrict__ bias, const float* __restrict__ res,
    float* __restrict__ C, int M, int N, int K)
{
    gemm_core(A, W, bias, res, C, M, N, K);
}

__global__ __launch_bounds__(256) void gemm_qkv(
    const float* __restrict__ Q, const float* __restrict__ K_,
    const float* __restrict__ V,
    const float* __restrict__ Wq, const float* __restrict__ Wk,
    const float* __restrict__ Wv,
    float* __restrict__ gq, float* __restrict__ gk, float* __restrict__ gv,
    int M, int N, int K)
{
    int z = blockIdx.z;
    const float* A = (z == 0) ? Q : (z == 1) ? K_ : V;
    const float* W = (z == 0) ? Wq : (z == 1) ? Wk : Wv;
    float* C       = (z == 0) ? gq : (z == 1) ? gk : gv;
    gemm_core(A, W, nullptr, nullptr, C, M, N, K);
}

// ---------------------------------------------------------------------------
// Tensor-core tf32 flash attention over reinterpreted [16, 2048, 64].
// 128 queries/block, 8 warps (16 q-rows each). K/V streamed in 64-key tiles.
// S = Q@K^T and O += P@V both on mma.m16n8k8.tf32.
// Smem strides: Qs/Ks 68 (frag bank = 4*gr+gc, conflict-free),
//               Vs 72 (B-frag bank = 8*gc+gr, conflict-free).
// Qs buffer is reused as per-warp P staging after Q fragments move to regs.
// ---------------------------------------------------------------------------
#define QS_STRIDE 68
#define KS_STRIDE 68
#define VS_STRIDE 72
#define ATTN_SMEM ((128*QS_STRIDE + 64*KS_STRIDE + 64*VS_STRIDE) * 4)

__global__ __launch_bounds__(256) void attn_tc(
    const float* __restrict__ qp, const float* __restrict__ kp,
    const float* __restrict__ vp, float* __restrict__ op)
{
    extern __shared__ unsigned smem[];
    unsigned* Qs = smem;                       // 128 x 68 (also P staging)
    unsigned* Ks = Qs + 128 * QS_STRIDE;       // 64 x 68
    unsigned* Vs = Ks + 64 * KS_STRIDE;        // 64 x 72

    const int tid  = threadIdx.x;
    const int lane = tid & 31;
    const int warp = tid >> 5;
    const int gr   = lane >> 2;
    const int gc   = lane & 3;
    const int g    = blockIdx.y;
    const int q0   = blockIdx.x * 128;
    const float scale = 0.04419417382415922f;  // 1/sqrt(512)

    // Stage Q (scaled, tf32): 128 rows x 16 float4 = 2048 float4, 8 per thread
    const float* qg = qp + ((size_t)g * 2048 + q0) * 64;
#pragma unroll
    for (int i = 0; i < 8; i++) {
        int idx = tid + i * 256;
        int row = idx >> 4, c4 = (idx & 15) * 4;
        float4 t = *(const float4*)(qg + (size_t)row * 64 + c4);
        uint4 u = make_uint4(f2tf(t.x * scale), f2tf(t.y * scale),
                             f2tf(t.z * scale), f2tf(t.w * scale));
        *(uint4*)&Qs[row * QS_STRIDE + c4] = u;
    }
    __syncthreads();

    // Q fragments into registers (8 k-chunks of dim)
    unsigned qa[8][4];
    {
        int r = warp * 16 + gr;
#pragma unroll
        for (int kk = 0; kk < 8; kk++) {
            qa[kk][0] = Qs[r * QS_STRIDE + kk * 8 + gc];
            qa[kk][1] = Qs[(r + 8) * QS_STRIDE + kk * 8 + gc];
            qa[kk][2] = Qs[r * QS_STRIDE + kk * 8 + gc + 4];
            qa[kk][3] = Qs[(r + 8) * QS_STRIDE + kk * 8 + gc + 4];
        }
    }
    // After this point each warp only touches its own 16 rows of Qs (as P).

    float oacc[8][4];
#pragma unroll
    for (int nt = 0; nt < 8; nt++)
#pragma unroll
        for (int i = 0; i < 4; i++) oacc[nt][i] = 0.f;
    float m0 = -1e30f, m1 = -1e30f, l0 = 0.f, l1 = 0.f;

    for (int kt = 0; kt < 32; kt++) {
        __syncthreads();
        const float* kg = kp + ((size_t)g * 2048 + kt * 64) * 64;
        const float* vg = vp + ((size_t)g * 2048 + kt * 64) * 64;
#pragma unroll
        for (int i = 0; i < 4; i++) {
            int idx = tid + i * 256;
            int row = idx >> 4, c4 = (idx & 15) * 4;
            float4 a = *(const float4*)(kg + (size_t)row * 64 + c4);
            *(uint4*)&Ks[row * KS_STRIDE + c4] =
                make_uint4(f2tf(a.x), f2tf(a.y), f2tf(a.z), f2tf(a.w));
            float4 b = *(const float4*)(vg + (size_t)row * 64 + c4);
            *(uint4*)&Vs[row * VS_STRIDE + c4] =
                make_uint4(f2tf(b.x), f2tf(b.y), f2tf(b.z), f2tf(b.w));
        }
        __syncthreads();

        // S = Q @ K^T : 16 x 64 per warp
        float sacc[8][4];
#pragma unroll
        for (int nt = 0; nt < 8; nt++)
#pragma unroll
            for (int i = 0; i < 4; i++) sacc[nt][i] = 0.f;
#pragma unroll
        for (int kk = 0; kk < 8; kk++) {
#pragma unroll
            for (int nt = 0; nt < 8; nt++) {
                unsigned b0 = Ks[(nt * 8 + gr) * KS_STRIDE + kk * 8 + gc];
                unsigned b1 = Ks[(nt * 8 + gr) * KS_STRIDE + kk * 8 + gc + 4];
                mma_tf32(sacc[nt], qa[kk], b0, b1, sacc[nt]);
            }
        }

        // Online softmax over the 64 keys of this tile
        float mloc0 = sacc[0][0], mloc1 = sacc[0][2];
#pragma unroll
        for (int nt = 0; nt < 8; nt++) {
            mloc0 = fmaxf(mloc0, fmaxf(sacc[nt][0], sacc[nt][1]));
            mloc1 = fmaxf(mloc1, fmaxf(sacc[nt][2], sacc[nt][3]));
        }
#pragma unroll
        for (int off = 1; off < 4; off <<= 1) {
            mloc0 = fmaxf(mloc0, __shfl_xor_sync(0xffffffffu, mloc0, off));
            mloc1 = fmaxf(mloc1, __shfl_xor_sync(0xffffffffu, mloc1, off));
        }
        float mn0 = fmaxf(m0, mloc0);
        float mn1 = fmaxf(m1, mloc1);
        float r0 = __expf(m0 - mn0);
        float r1 = __expf(m1 - mn1);

        float ps0 = 0.f, ps1 = 0.f;
        int r = warp * 16 + gr;
#pragma unroll
        for (int nt = 0; nt < 8; nt++) {
            float p00 = __expf(sacc[nt][0] - mn0);
            float p01 = __expf(sacc[nt][1] - mn0);
            float p10 = __expf(sacc[nt][2] - mn1);
            float p11 = __expf(sacc[nt][3] - mn1);
            ps0 += p00 + p01;
            ps1 += p10 + p11;
            Qs[r * QS_STRIDE + nt * 8 + 2 * gc]           = f2tf(p00);
            Qs[r * QS_STRIDE + nt * 8 + 2 * gc + 1]       = f2tf(p01);
            Qs[(r + 8) * QS_STRIDE + nt * 8 + 2 * gc]     = f2tf(p10);
            Qs[(r + 8) * QS_STRIDE + nt * 8 + 2 * gc + 1] = f2tf(p11);
        }
#pragma unroll
        for (int off = 1; off < 4; off <<= 1) {
            ps0 += __shfl_xor_sync(0xffffffffu, ps0, off);
            ps1 += __shfl_xor_sync(0xffffffffu, ps1, off);
        }
        l0 = l0 * r0 + ps0;
        l1 = l1 * r1 + ps1;
        m0 = mn0;
        m1 = mn1;
#pragma unroll
        for (int nt = 0; nt < 8; nt++) {
            oacc[nt][0] *= r0; oacc[nt][1] *= r0;
            oacc[nt][2] *= r1; oacc[nt][3] *= r1;
        }
        __syncwarp();

        // O += P @ V : P (16x64) from per-warp Qs rows, V B-frags from Vs
#pragma unroll
        for (int kk = 0; kk < 8; kk++) {
            unsigned pa[4];
            pa[0] = Qs[r * QS_STRIDE + kk * 8 + gc];
            pa[1] = Qs[(r + 8) * QS_STRIDE + kk * 8 + gc];
            pa[2] = Qs[r * QS_STRIDE + kk * 8 + gc + 4];
            pa[3] = Qs[(r + 8) * QS_STRIDE + kk * 8 + gc + 4];
#pragma unroll
            for (int nt = 0; nt < 8; nt++) {
                unsigned b0 = Vs[(kk * 8 + gc) * VS_STRIDE + nt * 8 + gr];
                unsigned b1 = Vs[(kk * 8 + gc + 4) * VS_STRIDE + nt * 8 + gr];
                mma_tf32(oacc[nt], pa, b0, b1, oacc[nt]);
            }
        }
    }

    // Normalize and write out
    float inv0 = 1.f / l0;
    float inv1 = 1.f / l1;
    int rr = q0 + warp * 16 + gr;
    float* og = op + ((size_t)g * 2048 + rr) * 64;
#pragma unroll
    for (int nt = 0; nt < 8; nt++) {
        *(float2*)(og + nt * 8 + 2 * gc) =
            make_float2(oacc[nt][0] * inv0, oacc[nt][1] * inv0);
        *(float2*)(og + 8 * 64 + nt * 8 + 2 * gc) =
            make_float2(oacc[nt][2] * inv1, oacc[nt][3] * inv1);
    }
}

// ---------------------------------------------------------------------------
// In-place layernorm over D=512 per row.
// ---------------------------------------------------------------------------
__global__ __launch_bounds__(512) void ln512(
    float* __restrict__ x, const float* __restrict__ gamma,
    const float* __restrict__ beta)
{
    const int row = blockIdx.x;
    const int tid = threadIdx.x;
    float* p = x + (size_t)row * 512;
    float v = p[tid];
    float s = v, sq = v * v;
#pragma unroll
    for (int off = 16; off > 0; off >>= 1) {
        s  += __shfl_xor_sync(0xffffffffu, s, off);
        sq += __shfl_xor_sync(0xffffffffu, sq, off);
    }
    __shared__ float ws[16], wq[16];
    __shared__ float stats[2];
    if ((tid & 31) == 0) { ws[tid >> 5] = s; wq[tid >> 5] = sq; }
    __syncthreads();
    if (tid == 0) {
        float S = 0.f, SQ = 0.f;
#pragma unroll
        for (int i = 0; i < 16; i++) { S += ws[i]; SQ += wq[i]; }
        float mu  = S * (1.f / 512.f);
        float var = SQ * (1.f / 512.f) - mu * mu;
        stats[0] = mu;
        stats[1] = rsqrtf(var + 1e-5f);
    }
    __syncthreads();
    p[tid] = (v - stats[0]) * stats[1] * gamma[tid] + beta[tid];
}

// ---------------------------------------------------------------------------
extern "C" void kernel_launch(void* const* d_in, const int* in_sizes, int n_in,
                              void* d_out, int out_size)
{
    (void)in_sizes; (void)n_in; (void)out_size;
    const float* Q     = (const float*)d_in[0];
    const float* K     = (const float*)d_in[1];
    const float* V     = (const float*)d_in[2];
    const float* Wq    = (const float*)d_in[4];
    const float* Wk    = (const float*)d_in[5];
    const float* Wv    = (const float*)d_in[6];
    const float* Wo    = (const float*)d_in[7];
    const float* bo    = (const float*)d_in[8];
    const float* gamma = (const float*)d_in[9];
    const float* beta  = (const float*)d_in[10];
    const float* W1    = (const float*)d_in[11];
    const float* b1    = (const float*)d_in[12];
    const float* W2    = (const float*)d_in[13];
    const float* b2    = (const float*)d_in[14];
    float* out = (float*)d_out;

    float* base = nullptr;
    cudaGetSymbolAddress((void**)&base, g_scratch);
    float* gq    = base;
    float* gk    = base + (size_t)NQ;
    float* gv    = base + (size_t)2 * NQ;
    float* gattn = base + (size_t)3 * NQ;
    float* gZ    = base + (size_t)4 * NQ;
    float* gff   = base + (size_t)5 * NQ;

    cudaFuncSetAttribute(attn_tc,
                         cudaFuncAttributeMaxDynamicSharedMemorySize,
                         ATTN_SMEM);

    // QKV projections (fused, 768 blocks)
    gemm_qkv<<<dim3(D_MODEL / 128, M_ROWS / 64, 3), 256>>>(
        Q, K, V, Wq, Wk, Wv, gq, gk, gv, M_ROWS, D_MODEL, D_MODEL);

    // Tensor-core attention over reinterpreted [16, 2048, 64]
    attn_tc<<<dim3(16, 16), 256, ATTN_SMEM>>>(gq, gk, gv, gattn);

    // Output projection + bias + residual (X = V), then LN -> Z
    gemm_one<<<dim3(D_MODEL / 128, M_ROWS / 64), 256>>>(
        gattn, Wo, bo, V, gZ, M_ROWS, D_MODEL, D_MODEL);
    ln512<<<M_ROWS, 512>>>(gZ, gamma, beta);

    // FFN (no activation in the reference)
    gemm_one<<<dim3(FF_DIM / 128, M_ROWS / 64), 256>>>(
        gZ, W1, b1, nullptr, gff, M_ROWS, FF_DIM, D_MODEL);
    gemm_one<<<dim3(D_MODEL / 128, M_ROWS / 64), 256>>>(
        gff, W2, b2, gZ, out, M_ROWS, D_MODEL, FF_DIM);
    ln512<<<M_ROWS, 512>>>(out, gamma, beta);
}